// round 15
// baseline (speedup 1.0000x reference)
#include <cuda_runtime.h>
#include <math_constants.h>

#define KVOL 27
#define C4   24                 // 96 channels = 24 float4
#define RPB  16                 // rows per block: 24*16 = 384 threads
#define NTHREADS (C4 * RPB)

// L2 policy: keep in_feat lines resident (evict-last priority).
__device__ __forceinline__ unsigned long long mk_keep_policy() {
    unsigned long long pol;
    asm("createpolicy.fractional.L2::evict_last.b64 %0, 1.0;" : "=l"(pol));
    return pol;
}

// Gather load: bypass L1 (.cg) + evict_last L2 policy.
__device__ __forceinline__ float4 ldg_gather(const float4* p, unsigned long long pol) {
    float4 v;
    asm("ld.global.cg.L2::cache_hint.v4.f32 {%0,%1,%2,%3}, [%4], %5;"
        : "=f"(v.x), "=f"(v.y), "=f"(v.z), "=f"(v.w) : "l"(p), "l"(pol));
    return v;
}

__device__ __forceinline__ void vmax(float4& m, const float4 v) {
    m.x = fmaxf(m.x, v.x);
    m.y = fmaxf(m.y, v.y);
    m.z = fmaxf(m.z, v.z);
    m.w = fmaxf(m.w, v.w);
}

// Gather B neighbors (indices from smem) with all B loads in flight, then reduce.
template <int B>
__device__ __forceinline__ void gather_batch(const float4* __restrict__ feat,
                                             const int* __restrict__ s_idx, int kb,
                                             float4& m, unsigned long long pol) {
    unsigned idx[B];
    #pragma unroll
    for (int j = 0; j < B; ++j)
        idx[j] = (unsigned)s_idx[kb + j];              // LDS broadcast (conflict-free)
    float4 v[B];
    #pragma unroll
    for (int j = 0; j < B; ++j)                        // B x 16B outstanding
        v[j] = ldg_gather(feat + (size_t)idx[j] * C4, pol);
    #pragma unroll
    for (int j = 0; j < B; ++j)
        vmax(m, v[j]);
}

// Converged geometry (36 warps/SM) + smem index staging, which frees the
// index registers and lets batching deepen to 10/10/7 within the 56-reg cap:
// 36 warps x 10 = 360 outstanding first-wave sectors/SM (vs 324 at 9/9/9).
__global__ __launch_bounds__(NTHREADS, 3)
void sparse_maxpool_kernel(const float4* __restrict__ in_feat,
                           const void* __restrict__ nmap,
                           float4* __restrict__ out,
                           int n_out, int n_in_rows) {
    __shared__ int s_bad;
    __shared__ int s_idx[RPB][KVOL];                   // 432 ints = 1.7 KB

    int t = threadIdx.y * C4 + threadIdx.x;
    if (t == 0) s_bad = 0;
    __syncthreads();
    if (t < 64) {                                      // dtype probe (512B, L2-hot)
        const long long* p = (const long long*)nmap;
        long long v = p[t];
        if (v < 0 || v >= (long long)n_in_rows) atomicOr(&s_bad, 1);
    }
    __syncthreads();
    int is64 = (s_bad == 0);

    int row0 = blockIdx.x * RPB;
    int nrows = min(RPB, n_out - row0);
    int nelem = nrows * KVOL;

    // ---- Cooperative, coalesced index staging into smem ----
    if (is64) {
        const long long* nmb = (const long long*)nmap + (size_t)row0 * KVOL;
        for (int e = t; e < nelem; e += NTHREADS)
            s_idx[e / KVOL][e % KVOL] = (int)__ldcs(&nmb[e]);
    } else {
        const int* nmb = (const int*)nmap + (size_t)row0 * KVOL;
        for (int e = t; e < nelem; e += NTHREADS)
            s_idx[e / KVOL][e % KVOL] = __ldcs(&nmb[e]);
    }
    __syncthreads();

    int row = row0 + threadIdx.y;
    if (row >= n_out) return;
    int c4 = threadIdx.x;                              // 0..23

    const unsigned long long pol = mk_keep_policy();
    const float4* feat_c = in_feat + c4;
    const int* my_idx = s_idx[threadIdx.y];

    float4 m = make_float4(-CUDART_INF_F, -CUDART_INF_F, -CUDART_INF_F, -CUDART_INF_F);
    gather_batch<10>(feat_c, my_idx, 0,  m, pol);
    gather_batch<10>(feat_c, my_idx, 10, m, pol);
    gather_batch<7 >(feat_c, my_idx, 20, m, pol);
    __stcs(out + (size_t)row * C4 + c4, m);            // streaming store
}

extern "C" void kernel_launch(void* const* d_in, const int* in_sizes, int n_in,
                              void* d_out, int out_size) {
    const float4* in_feat = (const float4*)d_in[0];
    const void*   nmap    = (const void*)d_in[1];
    float4*       out     = (float4*)d_out;

    int nmap_elems = in_sizes[1];                      // N_OUT * KVOL
    int n_out      = nmap_elems / KVOL;                // 100000
    int n_in_rows  = in_sizes[0] / 96;                 // 400000

    dim3 block(C4, RPB);
    int grid = (n_out + RPB - 1) / RPB;
    sparse_maxpool_kernel<<<grid, block>>>(in_feat, nmap, out, n_out, n_in_rows);
}